// round 10
// baseline (speedup 1.0000x reference)
#include <cuda_runtime.h>
#include <cstdint>

// Problem constants
#define BB 4
#define SS 4096
#define DD 2048
#define LL 3
#define TRIPLE (3 * DD)
#define MTOT (BB * SS)          // 16384

// GEMM tiling: CTA 128x128, 4 warps (2x2), warp tile 64x64, BK=64 (int8),
// 3-stage cp.async, 2 CTAs/SM. Tiles: 64B/row int8, XOR-16B-chunk swizzle.
#define BM 128
#define BN 128
#define BKI 64
#define NSTAGE 3
#define TILE_B (BM * BKI)               // 8192 bytes per plane tile
#define HH_STAGE (2 * TILE_B)           // 16384
#define MIX_STAGE (4 * TILE_B)          // 32768
#define HH_SMEM (NSTAGE * HH_STAGE)     // 49152
#define MIX_SMEM (NSTAGE * MIX_STAGE)   // 98304

// Scratch (__device__ globals: allocation-free rule)
__device__ float  g_BCx[(size_t)MTOT * TRIPLE];     // GEMM1 output fp32
__device__ int8_t g_Xh[(size_t)MTOT * DD];
__device__ int8_t g_Xl[(size_t)MTOT * DD];
__device__ int8_t g_Yh[(size_t)MTOT * DD];
__device__ int8_t g_Yl[(size_t)MTOT * DD];
__device__ int8_t g_WinH[(size_t)TRIPLE * DD];      // [N][K] transposed planes
__device__ int8_t g_WinL[(size_t)TRIPLE * DD];
__device__ int8_t g_WoutH[(size_t)DD * DD];
__device__ int8_t g_WoutL[(size_t)DD * DD];
__device__ float  g_sax[MTOT];
__device__ float  g_say[MTOT];
__device__ float  g_sbWin[TRIPLE];                  // colmax bits, then scale
__device__ float  g_sbWout[DD];

__device__ __forceinline__ uint32_t smem_u32(const void* p) {
    uint32_t a;
    asm("{ .reg .u64 t; cvta.to.shared.u64 t, %1; cvt.u32.u64 %0, t; }" : "=r"(a) : "l"(p));
    return a;
}

#define CP_ASYNC16(dst, src) \
    asm volatile("cp.async.cg.shared.global [%0], [%1], 16;" :: "r"(dst), "l"(src))
#define CP_COMMIT() asm volatile("cp.async.commit_group;" ::: "memory")
#define CP_WAIT1()  asm volatile("cp.async.wait_group 1;" ::: "memory")

__device__ __forceinline__ void imma(int c[4], const uint32_t a[4], const uint32_t b[2]) {
    asm volatile(
        "mma.sync.aligned.m16n8k32.row.col.s32.s8.s8.s32 "
        "{%0,%1,%2,%3}, {%4,%5,%6,%7}, {%8,%9}, {%0,%1,%2,%3};"
        : "+r"(c[0]), "+r"(c[1]), "+r"(c[2]), "+r"(c[3])
        : "r"(a[0]), "r"(a[1]), "r"(a[2]), "r"(a[3]), "r"(b[0]), "r"(b[1]));
}

// smem tile helpers: row r (0..127) of 64 bytes, 16B chunk c stored at c^((r>>1)&3)
__device__ __forceinline__ uint32_t sw_off(int r, int c) {
    return (uint32_t)(r * 64 + (((c) ^ ((r >> 1) & 3)) << 4));
}

// Load m16n8k32 A-frag (4 regs) for rows r, r+8 at k-half kh from plane base.
__device__ __forceinline__ void frag_a(uint32_t a[4], const char* P, int r, int kh, int lc) {
    const int c0 = kh * 2;
    a[0] = *(const uint32_t*)(P + sw_off(r,     c0)     + lc * 4);
    a[1] = *(const uint32_t*)(P + sw_off(r + 8, c0)     + lc * 4);
    a[2] = *(const uint32_t*)(P + sw_off(r,     c0 + 1) + lc * 4);
    a[3] = *(const uint32_t*)(P + sw_off(r + 8, c0 + 1) + lc * 4);
}
__device__ __forceinline__ void frag_b(uint32_t b[2], const char* P, int n, int kh, int lc) {
    const int c0 = kh * 2;
    b[0] = *(const uint32_t*)(P + sw_off(n, c0)     + lc * 4);
    b[1] = *(const uint32_t*)(P + sw_off(n, c0 + 1) + lc * 4);
}

// ---------------------------------------------------------------------------
// GEMM hh: C[M][N] = sa[m]*sb[n] * sum_k hA[m][k]*hB[n][k]
// ---------------------------------------------------------------------------
__global__ __launch_bounds__(128, 2)
void gemm_i8_hh(const int8_t* __restrict__ Ah, const int8_t* __restrict__ Bh,
                const float* __restrict__ sa, const float* __restrict__ sb,
                float* __restrict__ C, int N, int K) {
    extern __shared__ char smc[];
    const uint32_t smb = smem_u32(smc);

    const int tid  = threadIdx.x;
    const int wid  = tid >> 5;
    const int lane = tid & 31;
    const int warp_m = wid >> 1, warp_n = wid & 1;
    const int lr = lane >> 2, lc = lane & 3;

    const int brow = blockIdx.y * BM;
    const int bcol = blockIdx.x * BN;

    const int qrow = tid >> 2;      // 0..31
    const int qc   = tid & 3;       // chunk

    const int8_t* Apt = Ah + (size_t)brow * K;
    const int8_t* Bpt = Bh + (size_t)bcol * K;

    auto issue = [&](int kt, int buf) {
        uint32_t base = smb + (uint32_t)buf * HH_STAGE;
        #pragma unroll
        for (int i = 0; i < 4; i++) {
            int r = qrow + i * 32;
            CP_ASYNC16(base + sw_off(r, qc),
                       Apt + (size_t)r * K + kt * BKI + qc * 16);
            CP_ASYNC16(base + TILE_B + sw_off(r, qc),
                       Bpt + (size_t)r * K + kt * BKI + qc * 16);
        }
    };

    int acc[4][8][4];
    #pragma unroll
    for (int mi = 0; mi < 4; mi++)
        #pragma unroll
        for (int ni = 0; ni < 8; ni++)
            #pragma unroll
            for (int t = 0; t < 4; t++) acc[mi][ni][t] = 0;

    const int NK = K / BKI;
    issue(0, 0); CP_COMMIT();
    issue(1, 1); CP_COMMIT();

    int buf = 0;
    for (int kt = 0; kt < NK; kt++) {
        CP_WAIT1();
        __syncthreads();
        if (kt + 2 < NK) {
            int nb = buf + 2; if (nb >= NSTAGE) nb -= NSTAGE;
            issue(kt + 2, nb);
        }
        CP_COMMIT();

        const char* As = smc + (size_t)buf * HH_STAGE;
        const char* Bs = As + TILE_B;

        #pragma unroll
        for (int kh = 0; kh < 2; kh++) {
            uint32_t a[4][4], b[8][2];
            #pragma unroll
            for (int mi = 0; mi < 4; mi++)
                frag_a(a[mi], As, warp_m * 64 + mi * 16 + lr, kh, lc);
            #pragma unroll
            for (int ni = 0; ni < 8; ni++)
                frag_b(b[ni], Bs, warp_n * 64 + ni * 8 + lr, kh, lc);
            #pragma unroll
            for (int mi = 0; mi < 4; mi++)
                #pragma unroll
                for (int ni = 0; ni < 8; ni++)
                    imma(acc[mi][ni], a[mi], b[ni]);
        }
        if (++buf == NSTAGE) buf = 0;
    }

    #pragma unroll
    for (int mi = 0; mi < 4; mi++) {
        const int rg = brow + warp_m * 64 + mi * 16 + lr;
        const float sa0 = sa[rg], sa1 = sa[rg + 8];
        #pragma unroll
        for (int ni = 0; ni < 8; ni++) {
            const int c0 = bcol + warp_n * 64 + ni * 8 + lc * 2;
            float2 sbv = *(const float2*)(sb + c0);
            *(float2*)(C + (size_t)rg * N + c0) =
                make_float2(sa0 * sbv.x * (float)acc[mi][ni][0],
                            sa0 * sbv.y * (float)acc[mi][ni][1]);
            *(float2*)(C + (size_t)(rg + 8) * N + c0) =
                make_float2(sa1 * sbv.x * (float)acc[mi][ni][2],
                            sa1 * sbv.y * (float)acc[mi][ni][3]);
        }
    }
}

// ---------------------------------------------------------------------------
// GEMM mix: C[M][N] += sa*sb/254 * sum_k (hA*lB + lA*hB)
// ---------------------------------------------------------------------------
__global__ __launch_bounds__(128, 2)
void gemm_i8_mix(const int8_t* __restrict__ Ah, const int8_t* __restrict__ Al,
                 const int8_t* __restrict__ Bh, const int8_t* __restrict__ Bl,
                 const float* __restrict__ sa, const float* __restrict__ sb,
                 float* __restrict__ C, int N, int K) {
    extern __shared__ char smc[];
    const uint32_t smb = smem_u32(smc);

    const int tid  = threadIdx.x;
    const int wid  = tid >> 5;
    const int lane = tid & 31;
    const int warp_m = wid >> 1, warp_n = wid & 1;
    const int lr = lane >> 2, lc = lane & 3;

    const int brow = blockIdx.y * BM;
    const int bcol = blockIdx.x * BN;

    const int qrow = tid >> 2;
    const int qc   = tid & 3;

    const int8_t* Ahp = Ah + (size_t)brow * K;
    const int8_t* Alp = Al + (size_t)brow * K;
    const int8_t* Bhp = Bh + (size_t)bcol * K;
    const int8_t* Blp = Bl + (size_t)bcol * K;

    auto issue = [&](int kt, int buf) {
        uint32_t base = smb + (uint32_t)buf * MIX_STAGE;
        #pragma unroll
        for (int i = 0; i < 4; i++) {
            int r = qrow + i * 32;
            size_t go = (size_t)r * K + kt * BKI + qc * 16;
            uint32_t so = sw_off(r, qc);
            CP_ASYNC16(base + so,              Ahp + go);
            CP_ASYNC16(base + TILE_B + so,     Alp + go);
            CP_ASYNC16(base + 2 * TILE_B + so, Bhp + go);
            CP_ASYNC16(base + 3 * TILE_B + so, Blp + go);
        }
    };

    int acc[4][8][4];
    #pragma unroll
    for (int mi = 0; mi < 4; mi++)
        #pragma unroll
        for (int ni = 0; ni < 8; ni++)
            #pragma unroll
            for (int t = 0; t < 4; t++) acc[mi][ni][t] = 0;

    const int NK = K / BKI;
    issue(0, 0); CP_COMMIT();
    issue(1, 1); CP_COMMIT();

    int buf = 0;
    for (int kt = 0; kt < NK; kt++) {
        CP_WAIT1();
        __syncthreads();
        if (kt + 2 < NK) {
            int nb = buf + 2; if (nb >= NSTAGE) nb -= NSTAGE;
            issue(kt + 2, nb);
        }
        CP_COMMIT();

        const char* As_h = smc + (size_t)buf * MIX_STAGE;
        const char* As_l = As_h + TILE_B;
        const char* Bs_h = As_h + 2 * TILE_B;
        const char* Bs_l = As_h + 3 * TILE_B;

        #pragma unroll
        for (int kh = 0; kh < 2; kh++) {
            uint32_t ah[4][4], al[4][4], bh[8][2], bl[8][2];
            #pragma unroll
            for (int mi = 0; mi < 4; mi++) {
                frag_a(ah[mi], As_h, warp_m * 64 + mi * 16 + lr, kh, lc);
                frag_a(al[mi], As_l, warp_m * 64 + mi * 16 + lr, kh, lc);
            }
            #pragma unroll
            for (int ni = 0; ni < 8; ni++) {
                frag_b(bh[ni], Bs_h, warp_n * 64 + ni * 8 + lr, kh, lc);
                frag_b(bl[ni], Bs_l, warp_n * 64 + ni * 8 + lr, kh, lc);
            }
            #pragma unroll
            for (int mi = 0; mi < 4; mi++)
                #pragma unroll
                for (int ni = 0; ni < 8; ni++)
                    imma(acc[mi][ni], ah[mi], bl[ni]);
            #pragma unroll
            for (int mi = 0; mi < 4; mi++)
                #pragma unroll
                for (int ni = 0; ni < 8; ni++)
                    imma(acc[mi][ni], al[mi], bh[ni]);
        }
        if (++buf == NSTAGE) buf = 0;
    }

    const float r254 = 1.0f / 254.0f;
    #pragma unroll
    for (int mi = 0; mi < 4; mi++) {
        const int rg = brow + warp_m * 64 + mi * 16 + lr;
        const float sa0 = sa[rg] * r254, sa1 = sa[rg + 8] * r254;
        #pragma unroll
        for (int ni = 0; ni < 8; ni++) {
            const int c0 = bcol + warp_n * 64 + ni * 8 + lc * 2;
            float2 sbv = *(const float2*)(sb + c0);
            float2* p0 = (float2*)(C + (size_t)rg * N + c0);
            float2* p1 = (float2*)(C + (size_t)(rg + 8) * N + c0);
            float2 v0 = *p0, v1 = *p1;
            v0.x += sa0 * sbv.x * (float)acc[mi][ni][0];
            v0.y += sa0 * sbv.y * (float)acc[mi][ni][1];
            v1.x += sa1 * sbv.x * (float)acc[mi][ni][2];
            v1.y += sa1 * sbv.y * (float)acc[mi][ni][3];
            *p0 = v0; *p1 = v1;
        }
    }
}

// ---------------------------------------------------------------------------
// Quantization helpers
// ---------------------------------------------------------------------------
__device__ __forceinline__ uint32_t pack4(float q0, float q1, float q2, float q3,
                                          float* l0, float* l1, float* l2, float* l3) {
    int h0 = (int)rintf(q0), h1 = (int)rintf(q1), h2 = (int)rintf(q2), h3 = (int)rintf(q3);
    *l0 = (q0 - h0) * 254.0f; *l1 = (q1 - h1) * 254.0f;
    *l2 = (q2 - h2) * 254.0f; *l3 = (q3 - h3) * 254.0f;
    return (h0 & 0xFF) | ((h1 & 0xFF) << 8) | ((h2 & 0xFF) << 16) | ((h3 & 0xFF) << 24);
}
__device__ __forceinline__ uint32_t pack4i(float l0, float l1, float l2, float l3) {
    int a = (int)rintf(l0), b = (int)rintf(l1), c = (int)rintf(l2), d = (int)rintf(l3);
    return (a & 0xFF) | ((b & 0xFF) << 8) | ((c & 0xFF) << 16) | ((d & 0xFF) << 24);
}

__device__ __forceinline__ float block_max256(float v, float* sred) {
    #pragma unroll
    for (int o = 16; o > 0; o >>= 1)
        v = fmaxf(v, __shfl_xor_sync(0xFFFFFFFF, v, o));
    if ((threadIdx.x & 31) == 0) sred[threadIdx.x >> 5] = v;
    __syncthreads();
    float m = (threadIdx.x < 8) ? sred[threadIdx.x] : 0.0f;
    #pragma unroll
    for (int o = 4; o > 0; o >>= 1)
        m = fmaxf(m, __shfl_xor_sync(0xFFFFFFFF, m, o));
    if (threadIdx.x == 0) sred[0] = m;
    __syncthreads();
    return sred[0];
}

// Row-quantize x: per-row scale, two int8 planes. One block (256 thr) per row.
__global__ void rowquant_kernel(const float* __restrict__ in,
                                int8_t* __restrict__ H, int8_t* __restrict__ L,
                                float* __restrict__ sa) {
    __shared__ float sred[8];
    const int m = blockIdx.x;
    const float4* r4 = (const float4*)(in + (size_t)m * DD);
    const int t = threadIdx.x;

    float4 v0 = r4[t], v1 = r4[t + 256];
    float mx = fmaxf(fmaxf(fabsf(v0.x), fabsf(v0.y)), fmaxf(fabsf(v0.z), fabsf(v0.w)));
    mx = fmaxf(mx, fmaxf(fmaxf(fabsf(v1.x), fabsf(v1.y)), fmaxf(fabsf(v1.z), fabsf(v1.w))));
    mx = block_max256(mx, sred);

    const float inv = (mx > 0.0f) ? 127.0f / mx : 0.0f;
    if (t == 0) sa[m] = (mx > 0.0f) ? mx / 127.0f : 0.0f;

    uint32_t* Hw = (uint32_t*)(H + (size_t)m * DD);
    uint32_t* Lw = (uint32_t*)(L + (size_t)m * DD);
    float l0, l1, l2, l3;
    Hw[t] = pack4(v0.x * inv, v0.y * inv, v0.z * inv, v0.w * inv, &l0, &l1, &l2, &l3);
    Lw[t] = pack4i(l0, l1, l2, l3);
    Hw[t + 256] = pack4(v1.x * inv, v1.y * inv, v1.z * inv, v1.w * inv, &l0, &l1, &l2, &l3);
    Lw[t + 256] = pack4i(l0, l1, l2, l3);
}

// Column abs-max of W [K][N] via atomicMax on float bits (non-negative).
__global__ void colmax_kernel(const float* __restrict__ W, unsigned* __restrict__ mx,
                              int N) {
    const int n = blockIdx.x * 256 + threadIdx.x;
    const int k0 = blockIdx.y * 256;
    float m = 0.0f;
    for (int k = 0; k < 256; k++)
        m = fmaxf(m, fabsf(W[(size_t)(k0 + k) * N + n]));
    atomicMax(&mx[n], __float_as_uint(m));
}

__global__ void finalize_scale_kernel(float* __restrict__ s, int n) {
    int i = blockIdx.x * 256 + threadIdx.x;
    if (i >= n) return;
    float m = __uint_as_float(((unsigned*)s)[i]);
    s[i] = (m > 0.0f) ? m / 127.0f : 0.0f;
}

// Transpose + quantize W [K][N] -> planes [N][K]. Block (32,8), tile 32x32.
__global__ void wquant_kernel(const float* __restrict__ W, const float* __restrict__ sb,
                              int8_t* __restrict__ H, int8_t* __restrict__ L,
                              int N, int K) {
    __shared__ float t[32][33];
    const int kb = blockIdx.y * 32, nb = blockIdx.x * 32;
    const int tx = threadIdx.x, ty = threadIdx.y;
    #pragma unroll
    for (int j = 0; j < 4; j++)
        t[ty + 8 * j][tx] = W[(size_t)(kb + ty + 8 * j) * N + nb + tx];
    __syncthreads();
    #pragma unroll
    for (int j = 0; j < 4; j++) {
        const int n = nb + ty + 8 * j;
        const float s = sb[n];
        const float inv = (s > 0.0f) ? 1.0f / s : 0.0f;
        const float q = t[tx][ty + 8 * j] * inv;
        const int h = (int)rintf(q);
        const int l = (int)rintf((q - h) * 254.0f);
        H[(size_t)n * K + kb + tx] = (int8_t)h;
        L[(size_t)n * K + kb + tx] = (int8_t)l;
    }
}

// ---------------------------------------------------------------------------
// Fused conv + gates + row-quantize of y. One block (256 thr) per (b,s) row.
// ---------------------------------------------------------------------------
__global__ void conv_gate_quant_kernel(const float* __restrict__ conv_w,
                                       int8_t* __restrict__ H, int8_t* __restrict__ L,
                                       float* __restrict__ say) {
    __shared__ float sred[8];
    const int m = blockIdx.x;           // 0..16383
    const int s = m & (SS - 1);
    const int t = threadIdx.x;

    const float* bse = g_BCx + (size_t)m * TRIPLE;
    const float* bm1 = bse - TRIPLE;
    const float* bm2 = bse - 2 * TRIPLE;

    float o[8];
    float mx = 0.0f;
    #pragma unroll
    for (int g = 0; g < 2; g++) {
        const int d = t * 4 + g * 1024;
        #pragma unroll
        for (int j = 0; j < 4; j++) {
            const int dj = d + j;
            const float w0 = conv_w[dj * LL + 0];
            const float w1 = conv_w[dj * LL + 1];
            const float w2 = conv_w[dj * LL + 2];
            float bx_s  = bse[dj] * bse[2 * DD + dj];
            float bx_s1 = (s >= 1) ? bm1[dj] * bm1[2 * DD + dj] : 0.0f;
            float bx_s2 = (s >= 2) ? bm2[dj] * bm2[2 * DD + dj] : 0.0f;
            float conv = w2 * bx_s + w1 * bx_s1 + w0 * bx_s2;
            float yv = bse[DD + dj] * conv;
            o[g * 4 + j] = yv;
            mx = fmaxf(mx, fabsf(yv));
        }
    }
    mx = block_max256(mx, sred);
    const float inv = (mx > 0.0f) ? 127.0f / mx : 0.0f;
    if (t == 0) say[m] = (mx > 0.0f) ? mx / 127.0f : 0.0f;

    uint32_t* Hw = (uint32_t*)(H + (size_t)m * DD);
    uint32_t* Lw = (uint32_t*)(L + (size_t)m * DD);
    float l0, l1, l2, l3;
    Hw[t] = pack4(o[0] * inv, o[1] * inv, o[2] * inv, o[3] * inv, &l0, &l1, &l2, &l3);
    Lw[t] = pack4i(l0, l1, l2, l3);
    Hw[t + 256] = pack4(o[4] * inv, o[5] * inv, o[6] * inv, o[7] * inv, &l0, &l1, &l2, &l3);
    Lw[t + 256] = pack4i(l0, l1, l2, l3);
}

// ---------------------------------------------------------------------------
extern "C" void kernel_launch(void* const* d_in, const int* in_sizes, int n_in,
                              void* d_out, int out_size) {
    const float* x      = (const float*)d_in[0];
    const float* W_in   = (const float*)d_in[1];
    const float* conv_w = (const float*)d_in[2];
    const float* W_out  = (const float*)d_in[3];
    float*       out    = (float*)d_out;

    float *BCx, *sax, *say, *sbWin, *sbWout;
    int8_t *Xh, *Xl, *Yh, *Yl, *WinH, *WinL, *WoutH, *WoutL;
    cudaGetSymbolAddress((void**)&BCx,    g_BCx);
    cudaGetSymbolAddress((void**)&Xh,     g_Xh);
    cudaGetSymbolAddress((void**)&Xl,     g_Xl);
    cudaGetSymbolAddress((void**)&Yh,     g_Yh);
    cudaGetSymbolAddress((void**)&Yl,     g_Yl);
    cudaGetSymbolAddress((void**)&WinH,   g_WinH);
    cudaGetSymbolAddress((void**)&WinL,   g_WinL);
    cudaGetSymbolAddress((void**)&WoutH,  g_WoutH);
    cudaGetSymbolAddress((void**)&WoutL,  g_WoutL);
    cudaGetSymbolAddress((void**)&sax,    g_sax);
    cudaGetSymbolAddress((void**)&say,    g_say);
    cudaGetSymbolAddress((void**)&sbWin,  g_sbWin);
    cudaGetSymbolAddress((void**)&sbWout, g_sbWout);

    cudaFuncSetAttribute(gemm_i8_hh,  cudaFuncAttributeMaxDynamicSharedMemorySize, HH_SMEM);
    cudaFuncSetAttribute(gemm_i8_mix, cudaFuncAttributeMaxDynamicSharedMemorySize, MIX_SMEM);

    // ---- Quantize inputs ----
    cudaMemsetAsync(sbWin, 0, TRIPLE * sizeof(float));
    cudaMemsetAsync(sbWout, 0, DD * sizeof(float));
    rowquant_kernel<<<MTOT, 256>>>(x, Xh, Xl, sax);
    colmax_kernel<<<dim3(TRIPLE / 256, DD / 256), 256>>>(W_in, (unsigned*)sbWin, TRIPLE);
    colmax_kernel<<<dim3(DD / 256, DD / 256), 256>>>(W_out, (unsigned*)sbWout, DD);
    finalize_scale_kernel<<<(TRIPLE + 255) / 256, 256>>>(sbWin, TRIPLE);
    finalize_scale_kernel<<<(DD + 255) / 256, 256>>>(sbWout, DD);
    wquant_kernel<<<dim3(TRIPLE / 32, DD / 32), dim3(32, 8)>>>(W_in, sbWin, WinH, WinL, TRIPLE, DD);
    wquant_kernel<<<dim3(DD / 32, DD / 32), dim3(32, 8)>>>(W_out, sbWout, WoutH, WoutL, DD, DD);

    // ---- GEMM1: BCx = x @ W_in ----
    gemm_i8_hh<<<dim3(TRIPLE / BN, MTOT / BM), 128, HH_SMEM>>>(Xh, WinH, sax, sbWin, BCx, TRIPLE, DD);
    gemm_i8_mix<<<dim3(TRIPLE / BN, MTOT / BM), 128, MIX_SMEM>>>(Xh, Xl, WinH, WinL, sax, sbWin, BCx, TRIPLE, DD);

    // ---- Conv + gates + quantize y ----
    conv_gate_quant_kernel<<<MTOT, 256>>>(conv_w, Yh, Yl, say);

    // ---- GEMM2: out = y @ W_out ----
    gemm_i8_hh<<<dim3(DD / BN, MTOT / BM), 128, HH_SMEM>>>(Yh, WoutH, say, sbWout, out, DD, DD);
    gemm_i8_mix<<<dim3(DD / BN, MTOT / BM), 128, MIX_SMEM>>>(Yh, Yl, WoutH, WoutL, say, sbWout, out, DD, DD);
}

// round 11
// speedup vs baseline: 3.6485x; 3.6485x over previous
#include <cuda_runtime.h>
#include <cstdint>

// Problem constants
#define BB 4
#define SS 4096
#define DD 2048
#define LL 3
#define TRIPLE (3 * DD)
#define MTOT (BB * SS)          // 16384

// GEMM tiling: CTA 128x128, 4 warps (2x2), warp tile 64x64, BK=32,
// 3-stage cp.async, 2 CTAs/SM, single barrier per k-tile.
// A smem: [128][36] natural k order (round-9 proven).
// B smem: [16][264] pair-interleaved: phys row (ks*4+p) col 2n+h holds
//         logical B[k = 8ks+p+4h][n]  -> one LDS.64 per B fragment.
#define BM 128
#define BN 128
#define BK 32
#define NSTAGE 3
#define AST 36
#define BST 264
#define A_SM (BM * AST)         // 4608 floats
#define B_SM (16 * BST)         // 4224 floats
#define STG_FLT (A_SM + B_SM)   // 8832 floats
#define SMEM_BYTES (NSTAGE * STG_FLT * 4)   // 105984 B

// Scratch (__device__ globals: allocation-free rule)
__device__ float g_BCx[(size_t)MTOT * TRIPLE];   // [b,s,3D] = [B_gate|C_gate|x_proj]
__device__ float g_y[(size_t)MTOT * DD];         // GEMM2 A (tf32-rounded)
__device__ float g_xc[(size_t)MTOT * DD];        // x tf32-rounded
__device__ float g_Win[(size_t)DD * TRIPLE];     // W_in  interleaved [K/2][2N]
__device__ float g_Wout[(size_t)DD * DD];        // W_out interleaved [K/2][2N]

__device__ __forceinline__ float f2tf32(float x) {
    float r;
    asm("cvt.rna.tf32.f32 %0, %1;" : "=f"(r) : "f"(x));
    return r;
}

__device__ __forceinline__ uint32_t smem_u32(const void* p) {
    uint32_t a;
    asm("{ .reg .u64 t; cvta.to.shared.u64 t, %1; cvt.u32.u64 %0, t; }" : "=r"(a) : "l"(p));
    return a;
}

#define CP_ASYNC16(dst, src) \
    asm volatile("cp.async.cg.shared.global [%0], [%1], 16;" :: "r"(dst), "l"(src))
#define CP_COMMIT() asm volatile("cp.async.commit_group;" ::: "memory")
#define CP_WAIT1()  asm volatile("cp.async.wait_group 1;" ::: "memory")

__device__ __forceinline__ void mma_tf32(float c[4], const uint32_t a[4], const uint32_t b[2]) {
    asm volatile(
        "mma.sync.aligned.m16n8k8.row.col.f32.tf32.tf32.f32 "
        "{%0,%1,%2,%3}, {%4,%5,%6,%7}, {%8,%9}, {%0,%1,%2,%3};"
        : "+f"(c[0]), "+f"(c[1]), "+f"(c[2]), "+f"(c[3])
        : "r"(a[0]), "r"(a[1]), "r"(a[2]), "r"(a[3]), "r"(b[0]), "r"(b[1]));
}

// ---------------------------------------------------------------------------
// TF32 mma.sync GEMM: C[M,N] = A[M,K] @ B[K,N].
// A row-major fp32 (tf32-pre-rounded, natural k order).
// B pre-interleaved [K/2][2N] (tf32-pre-rounded).
// 128 threads, warps 2x2, warp tile 64x64. Single barrier per k-tile.
// ---------------------------------------------------------------------------
__global__ __launch_bounds__(128, 2)
void tf32_gemm(const float* __restrict__ A, const float* __restrict__ B,
               float* __restrict__ C, int N, int K) {
    extern __shared__ float sm[];
    const uint32_t smb = smem_u32(sm);

    const int tid    = threadIdx.x;
    const int wid    = tid >> 5;
    const int lane   = tid & 31;
    const int warp_m = wid >> 1;      // 0..1
    const int warp_n = wid & 1;       // 0..1
    const int lr     = lane >> 2;     // 0..7
    const int lc     = lane & 3;      // 0..3

    const int brow = blockIdx.y * BM;
    const int bcol = blockIdx.x * BN;

    const float* Ap = A + (size_t)brow * K;
    const float* Bp = B + 2 * (size_t)bcol;
    const size_t brs = 2 * (size_t)N;   // interleaved B row stride (floats)

    // cp.async coords (128 threads)
    const int arow0 = tid >> 3;             // +i*16
    const int akc   = (tid & 7) * 4;
    const int brw   = tid >> 3;             // B phys row 0..15
    const int bcc   = (tid & 7) * 4;        // +i*32 floats

    auto issue = [&](int kt, int buf) {
        uint32_t as = smb + (uint32_t)buf * STG_FLT * 4;
        uint32_t bs = as + A_SM * 4;
        #pragma unroll
        for (int i = 0; i < 8; i++) {
            int m = arow0 + i * 16;
            CP_ASYNC16(as + (uint32_t)(m * AST + akc) * 4,
                       Ap + (size_t)m * K + kt * BK + akc);
        }
        const float* bsrc = Bp + (size_t)(16 * kt + brw) * brs;
        #pragma unroll
        for (int i = 0; i < 8; i++) {
            int c = bcc + i * 32;
            CP_ASYNC16(bs + (uint32_t)(brw * BST + c) * 4, bsrc + c);
        }
    };

    float acc[4][8][4];
    #pragma unroll
    for (int mi = 0; mi < 4; mi++)
        #pragma unroll
        for (int ni = 0; ni < 8; ni++)
            #pragma unroll
            for (int t = 0; t < 4; t++)
                acc[mi][ni][t] = 0.0f;

    const int NK = K / BK;

    issue(0, 0); CP_COMMIT();
    issue(1, 1); CP_COMMIT();

    int buf = 0;
    for (int kt = 0; kt < NK; kt++) {
        CP_WAIT1();
        __syncthreads();

        if (kt + 2 < NK) {
            int nbuf = buf + 2; if (nbuf >= NSTAGE) nbuf -= NSTAGE;
            issue(kt + 2, nbuf);
        }
        CP_COMMIT();

        const float* As = sm + (size_t)buf * STG_FLT;
        const float* Bs = As + A_SM;

        #pragma unroll
        for (int ks = 0; ks < 4; ks++) {
            const int k0 = ks * 8;
            uint32_t a[4][4];
            #pragma unroll
            for (int mi = 0; mi < 4; mi++) {
                const int base = (warp_m * 64 + mi * 16 + lr) * AST + k0 + lc;
                a[mi][0] = __float_as_uint(As[base]);
                a[mi][1] = __float_as_uint(As[base + 8 * AST]);
                a[mi][2] = __float_as_uint(As[base + 4]);
                a[mi][3] = __float_as_uint(As[base + 8 * AST + 4]);
            }
            uint32_t b[8][2];
            #pragma unroll
            for (int ni = 0; ni < 8; ni++) {
                const int n = warp_n * 64 + ni * 8 + lr;
                float2 v = *(const float2*)(Bs + (ks * 4 + lc) * BST + 2 * n);
                b[ni][0] = __float_as_uint(v.x);
                b[ni][1] = __float_as_uint(v.y);
            }
            #pragma unroll
            for (int mi = 0; mi < 4; mi++)
                #pragma unroll
                for (int ni = 0; ni < 8; ni++)
                    mma_tf32(acc[mi][ni], a[mi], b[ni]);
        }

        if (++buf == NSTAGE) buf = 0;
    }

    // Epilogue
    #pragma unroll
    for (int mi = 0; mi < 4; mi++) {
        #pragma unroll
        for (int ni = 0; ni < 8; ni++) {
            const int r0 = brow + warp_m * 64 + mi * 16 + lr;
            const int c0 = bcol + warp_n * 64 + ni * 8 + lc * 2;
            *(float2*)(C + (size_t)r0 * N + c0)       = make_float2(acc[mi][ni][0], acc[mi][ni][1]);
            *(float2*)(C + (size_t)(r0 + 8) * N + c0) = make_float2(acc[mi][ni][2], acc[mi][ni][3]);
        }
    }
}

// ---------------------------------------------------------------------------
// Elementwise tf32 rounding (float4 vectorized) — for x and y inputs
// ---------------------------------------------------------------------------
__global__ void cvt_tf32_kernel(const float* __restrict__ in, float* __restrict__ out,
                                size_t n4) {
    size_t i = (size_t)blockIdx.x * blockDim.x + threadIdx.x;
    if (i >= n4) return;
    float4 v = ((const float4*)in)[i];
    v.x = f2tf32(v.x); v.y = f2tf32(v.y); v.z = f2tf32(v.z); v.w = f2tf32(v.w);
    ((float4*)out)[i] = v;
}

// ---------------------------------------------------------------------------
// W [K][N] -> pair-interleaved [K/2][2N]: out[kb*4+p][2n+h] = tf32(W[kb*8+p+4h][n])
// Block: one k-block (8 rows) x 256 n-cols. 256 threads. (Verified round 7.)
// ---------------------------------------------------------------------------
__global__ void wtrans_kernel(const float* __restrict__ in, float* __restrict__ out,
                              int N) {
    __shared__ float s[8][257];
    const int kb = blockIdx.y;
    const int n0 = blockIdx.x * 256;
    const int tid = threadIdx.x;

    #pragma unroll
    for (int j = 0; j < 8; j++)
        s[j][tid] = f2tf32(in[(size_t)(kb * 8 + j) * N + n0 + tid]);
    __syncthreads();

    const int p  = tid >> 6;        // 0..3
    const int j0 = tid & 63;
    #pragma unroll
    for (int h = 0; h < 2; h++) {
        int j = j0 + h * 64;        // n-pair index 0..127
        float4 v = make_float4(s[p][2 * j], s[p + 4][2 * j],
                               s[p][2 * j + 1], s[p + 4][2 * j + 1]);
        *(float4*)(out + (size_t)(kb * 4 + p) * (2 * N) + 2 * n0 + 4 * j) = v;
    }
}

// ---------------------------------------------------------------------------
// Fused: Bx = B_gate*x_proj; causal L=3 depthwise conv; y = tf32(C_gate*conv)
// (round-9 version, natural y layout — A path of GEMM2 unchanged)
// ---------------------------------------------------------------------------
__global__ void conv_gate_kernel(const float* __restrict__ conv_w,
                                 float* __restrict__ y) {
    const size_t total = (size_t)MTOT * (DD / 4);
    size_t idx = (size_t)blockIdx.x * blockDim.x + threadIdx.x;
    if (idx >= total) return;

    const int    d4 = (int)(idx % (DD / 4));
    const size_t bs = idx / (DD / 4);
    const int    s  = (int)(bs % SS);
    const int    d  = d4 * 4;

    const float* bse = g_BCx + bs * TRIPLE;
    const float* bm1 = bse - TRIPLE;
    const float* bm2 = bse - 2 * TRIPLE;

    float out[4];
    #pragma unroll
    for (int j = 0; j < 4; j++) {
        const int dj = d + j;
        const float w0 = conv_w[dj * LL + 0];
        const float w1 = conv_w[dj * LL + 1];
        const float w2 = conv_w[dj * LL + 2];

        float bx_s  = bse[dj] * bse[2 * DD + dj];
        float bx_s1 = (s >= 1) ? bm1[dj] * bm1[2 * DD + dj] : 0.0f;
        float bx_s2 = (s >= 2) ? bm2[dj] * bm2[2 * DD + dj] : 0.0f;

        float conv = w2 * bx_s + w1 * bx_s1 + w0 * bx_s2;
        out[j] = f2tf32(bse[DD + dj] * conv);
    }
    *(float4*)(y + bs * DD + d) = *(float4*)out;
}

// ---------------------------------------------------------------------------
extern "C" void kernel_launch(void* const* d_in, const int* in_sizes, int n_in,
                              void* d_out, int out_size) {
    const float* x      = (const float*)d_in[0];
    const float* W_in   = (const float*)d_in[1];
    const float* conv_w = (const float*)d_in[2];
    const float* W_out  = (const float*)d_in[3];
    float*       out    = (float*)d_out;

    float *BCx, *y, *xc, *Win, *Wout;
    cudaGetSymbolAddress((void**)&BCx,  g_BCx);
    cudaGetSymbolAddress((void**)&y,    g_y);
    cudaGetSymbolAddress((void**)&xc,   g_xc);
    cudaGetSymbolAddress((void**)&Win,  g_Win);
    cudaGetSymbolAddress((void**)&Wout, g_Wout);

    cudaFuncSetAttribute(tf32_gemm, cudaFuncAttributeMaxDynamicSharedMemorySize, SMEM_BYTES);

    // Pre-passes: tf32 rounding (x) + weight interleave transforms
    {
        size_t n4 = (size_t)MTOT * DD / 4;
        cvt_tf32_kernel<<<(unsigned)((n4 + 255) / 256), 256>>>(x, xc, n4);
        wtrans_kernel<<<dim3(TRIPLE / 256, DD / 8), 256>>>(W_in, Win, TRIPLE);
        wtrans_kernel<<<dim3(DD / 256, DD / 8), 256>>>(W_out, Wout, DD);
    }

    // GEMM1: BCx = x' @ W_in   (16384 x 2048) @ (2048 x 6144)
    tf32_gemm<<<dim3(TRIPLE / BN, MTOT / BM), 128, SMEM_BYTES>>>(xc, Win, BCx, TRIPLE, DD);

    // Conv + gates -> y (tf32-rounded)
    {
        size_t total = (size_t)MTOT * (DD / 4);
        conv_gate_kernel<<<(unsigned)((total + 255) / 256), 256>>>(conv_w, y);
    }

    // GEMM2: out = y @ W_out   (16384 x 2048) @ (2048 x 2048)
    tf32_gemm<<<dim3(DD / BN, MTOT / BM), 128, SMEM_BYTES>>>(y, Wout, out, DD, DD);
}

// round 12
// speedup vs baseline: 3.7512x; 1.0281x over previous
#include <cuda_runtime.h>
#include <cstdint>

// Problem constants
#define BB 4
#define SS 4096
#define DD 2048
#define LL 3
#define TRIPLE (3 * DD)
#define MTOT (BB * SS)          // 16384

// GEMM tiling: CTA 128x128, 4 warps (2x2), warp tile 64x64, BK=32,
// 3-stage cp.async, 2 CTAs/SM, single barrier per k-tile.
// A smem: [128][36] natural k order. B smem: [16][264] pair-interleaved.
#define BM 128
#define BN 128
#define BK 32
#define NSTAGE 3
#define AST 36
#define BST 264
#define A_SM (BM * AST)         // 4608 floats
#define B_SM (16 * BST)         // 4224 floats
#define STG_FLT (A_SM + B_SM)   // 8832 floats
#define SMEM_BYTES (NSTAGE * STG_FLT * 4)   // 105984 B

// Scratch (__device__ globals: allocation-free rule)
__device__ float g_Bx[(size_t)MTOT * DD];        // B_gate*x_proj (from GEMM1 epilogue)
__device__ float g_Cg[(size_t)MTOT * DD];        // C_gate
__device__ float g_y[(size_t)MTOT * DD];         // GEMM2 A (tf32-rounded)
__device__ float g_xc[(size_t)MTOT * DD];        // x tf32-rounded
__device__ float g_Win[(size_t)DD * TRIPLE];     // W_in  remapped+interleaved [K/2][2N]
__device__ float g_Wout[(size_t)DD * DD];        // W_out interleaved [K/2][2N]

__device__ __forceinline__ float f2tf32(float x) {
    float r;
    asm("cvt.rna.tf32.f32 %0, %1;" : "=f"(r) : "f"(x));
    return r;
}

__device__ __forceinline__ uint32_t smem_u32(const void* p) {
    uint32_t a;
    asm("{ .reg .u64 t; cvta.to.shared.u64 t, %1; cvt.u32.u64 %0, t; }" : "=r"(a) : "l"(p));
    return a;
}

#define CP_ASYNC16(dst, src) \
    asm volatile("cp.async.cg.shared.global [%0], [%1], 16;" :: "r"(dst), "l"(src))
#define CP_COMMIT() asm volatile("cp.async.commit_group;" ::: "memory")
#define CP_WAIT1()  asm volatile("cp.async.wait_group 1;" ::: "memory")

__device__ __forceinline__ void mma_tf32(float c[4], const uint32_t a[4], const uint32_t b[2]) {
    asm volatile(
        "mma.sync.aligned.m16n8k8.row.col.f32.tf32.tf32.f32 "
        "{%0,%1,%2,%3}, {%4,%5,%6,%7}, {%8,%9}, {%0,%1,%2,%3};"
        : "+f"(c[0]), "+f"(c[1]), "+f"(c[2]), "+f"(c[3])
        : "r"(a[0]), "r"(a[1]), "r"(a[2]), "r"(a[3]), "r"(b[0]), "r"(b[1]));
}

// ---------------------------------------------------------------------------
// TF32 mma.sync GEMM. A row-major (tf32-pre-rounded), B pre-interleaved
// [K/2][2N]. mode 0: plain C[M][N] write.
// mode 1 (GEMM1 gated): N-cols are remapped so cols 2d/2d+1 (n<4096) hold
//   (B_gate_d, x_proj_d) and cols 4096+d hold C_gate_d. Epilogue writes
//   Bx[d] = accEven*accOdd to CBx, and C_gate naturally to CCg.
// ---------------------------------------------------------------------------
__global__ __launch_bounds__(128, 2)
void tf32_gemm(const float* __restrict__ A, const float* __restrict__ B,
               float* __restrict__ C, float* __restrict__ CBx,
               float* __restrict__ CCg, int N, int K, int mode) {
    extern __shared__ float sm[];
    const uint32_t smb = smem_u32(sm);

    const int tid    = threadIdx.x;
    const int wid    = tid >> 5;
    const int lane   = tid & 31;
    const int warp_m = wid >> 1;      // 0..1
    const int warp_n = wid & 1;       // 0..1
    const int lr     = lane >> 2;     // 0..7
    const int lc     = lane & 3;      // 0..3

    const int brow = blockIdx.y * BM;
    const int bcol = blockIdx.x * BN;

    const float* Ap = A + (size_t)brow * K;
    const float* Bp = B + 2 * (size_t)bcol;
    const size_t brs = 2 * (size_t)N;   // interleaved B row stride (floats)

    const int arow0 = tid >> 3;
    const int akc   = (tid & 7) * 4;
    const int brw   = tid >> 3;
    const int bcc   = (tid & 7) * 4;

    auto issue = [&](int kt, int buf) {
        uint32_t as = smb + (uint32_t)buf * STG_FLT * 4;
        uint32_t bs = as + A_SM * 4;
        #pragma unroll
        for (int i = 0; i < 8; i++) {
            int m = arow0 + i * 16;
            CP_ASYNC16(as + (uint32_t)(m * AST + akc) * 4,
                       Ap + (size_t)m * K + kt * BK + akc);
        }
        const float* bsrc = Bp + (size_t)(16 * kt + brw) * brs;
        #pragma unroll
        for (int i = 0; i < 8; i++) {
            int c = bcc + i * 32;
            CP_ASYNC16(bs + (uint32_t)(brw * BST + c) * 4, bsrc + c);
        }
    };

    float acc[4][8][4];
    #pragma unroll
    for (int mi = 0; mi < 4; mi++)
        #pragma unroll
        for (int ni = 0; ni < 8; ni++)
            #pragma unroll
            for (int t = 0; t < 4; t++)
                acc[mi][ni][t] = 0.0f;

    const int NK = K / BK;

    issue(0, 0); CP_COMMIT();
    issue(1, 1); CP_COMMIT();

    int buf = 0;
    for (int kt = 0; kt < NK; kt++) {
        CP_WAIT1();
        __syncthreads();

        if (kt + 2 < NK) {
            int nbuf = buf + 2; if (nbuf >= NSTAGE) nbuf -= NSTAGE;
            issue(kt + 2, nbuf);
        }
        CP_COMMIT();

        const float* As = sm + (size_t)buf * STG_FLT;
        const float* Bs = As + A_SM;

        #pragma unroll
        for (int ks = 0; ks < 4; ks++) {
            const int k0 = ks * 8;
            uint32_t a[4][4];
            #pragma unroll
            for (int mi = 0; mi < 4; mi++) {
                const int base = (warp_m * 64 + mi * 16 + lr) * AST + k0 + lc;
                a[mi][0] = __float_as_uint(As[base]);
                a[mi][1] = __float_as_uint(As[base + 8 * AST]);
                a[mi][2] = __float_as_uint(As[base + 4]);
                a[mi][3] = __float_as_uint(As[base + 8 * AST + 4]);
            }
            uint32_t b[8][2];
            #pragma unroll
            for (int ni = 0; ni < 8; ni++) {
                const int n = warp_n * 64 + ni * 8 + lr;
                float2 v = *(const float2*)(Bs + (ks * 4 + lc) * BST + 2 * n);
                b[ni][0] = __float_as_uint(v.x);
                b[ni][1] = __float_as_uint(v.y);
            }
            #pragma unroll
            for (int mi = 0; mi < 4; mi++)
                #pragma unroll
                for (int ni = 0; ni < 8; ni++)
                    mma_tf32(acc[mi][ni], a[mi], b[ni]);
        }

        if (++buf == NSTAGE) buf = 0;
    }

    // Epilogue
    if (mode == 0) {
        #pragma unroll
        for (int mi = 0; mi < 4; mi++) {
            #pragma unroll
            for (int ni = 0; ni < 8; ni++) {
                const int r0 = brow + warp_m * 64 + mi * 16 + lr;
                const int c0 = bcol + warp_n * 64 + ni * 8 + lc * 2;
                *(float2*)(C + (size_t)r0 * N + c0)       = make_float2(acc[mi][ni][0], acc[mi][ni][1]);
                *(float2*)(C + (size_t)(r0 + 8) * N + c0) = make_float2(acc[mi][ni][2], acc[mi][ni][3]);
            }
        }
    } else if (bcol < 2 * DD) {
        // gated pairs: thread cols (c0, c0+1) = (B_gate_d, x_proj_d), d = c0/2
        #pragma unroll
        for (int mi = 0; mi < 4; mi++) {
            #pragma unroll
            for (int ni = 0; ni < 8; ni++) {
                const int r0 = brow + warp_m * 64 + mi * 16 + lr;
                const int d  = (bcol + warp_n * 64 + ni * 8 + lc * 2) >> 1;
                CBx[(size_t)r0 * DD + d]       = acc[mi][ni][0] * acc[mi][ni][1];
                CBx[(size_t)(r0 + 8) * DD + d] = acc[mi][ni][2] * acc[mi][ni][3];
            }
        }
    } else {
        #pragma unroll
        for (int mi = 0; mi < 4; mi++) {
            #pragma unroll
            for (int ni = 0; ni < 8; ni++) {
                const int r0 = brow + warp_m * 64 + mi * 16 + lr;
                const int c0 = bcol - 2 * DD + warp_n * 64 + ni * 8 + lc * 2;
                *(float2*)(CCg + (size_t)r0 * DD + c0)       = make_float2(acc[mi][ni][0], acc[mi][ni][1]);
                *(float2*)(CCg + (size_t)(r0 + 8) * DD + c0) = make_float2(acc[mi][ni][2], acc[mi][ni][3]);
            }
        }
    }
}

// ---------------------------------------------------------------------------
// Elementwise tf32 rounding (float4 vectorized)
// ---------------------------------------------------------------------------
__global__ void cvt_tf32_kernel(const float* __restrict__ in, float* __restrict__ out,
                                size_t n4) {
    size_t i = (size_t)blockIdx.x * blockDim.x + threadIdx.x;
    if (i >= n4) return;
    float4 v = ((const float4*)in)[i];
    v.x = f2tf32(v.x); v.y = f2tf32(v.y); v.z = f2tf32(v.z); v.w = f2tf32(v.w);
    ((float4*)out)[i] = v;
}

// ---------------------------------------------------------------------------
// W [K][N] -> pair-interleaved [K/2][2N'], with optional source-column remap
// (for GEMM1's gated layout):
//   remap(n) = n<4096 ? (n odd ? 2D+n/2 : n/2) : D + (n-4096)
// out[kb*4+p][2n+h] = tf32(W[kb*8+p+4h][remap(n)]).
// Block: one k-block (8 rows) x 256 output cols. 256 threads.
// ---------------------------------------------------------------------------
template <int REMAP>
__global__ void wtrans_kernel(const float* __restrict__ in, float* __restrict__ out,
                              int N) {
    __shared__ float s[8][257];
    const int kb = blockIdx.y;
    const int n0 = blockIdx.x * 256;
    const int tid = threadIdx.x;

    int n = n0 + tid;
    int src;
    if (REMAP) {
        src = (n < 2 * DD) ? ((n & 1) ? 2 * DD + (n >> 1) : (n >> 1))
                           : DD + (n - 2 * DD);
    } else {
        src = n;
    }
    #pragma unroll
    for (int j = 0; j < 8; j++)
        s[j][tid] = f2tf32(in[(size_t)(kb * 8 + j) * N + src]);
    __syncthreads();

    const int p  = tid >> 6;        // 0..3
    const int j0 = tid & 63;
    #pragma unroll
    for (int h = 0; h < 2; h++) {
        int j = j0 + h * 64;        // n-pair index 0..127
        float4 v = make_float4(s[p][2 * j], s[p + 4][2 * j],
                               s[p][2 * j + 1], s[p + 4][2 * j + 1]);
        *(float4*)(out + (size_t)(kb * 4 + p) * (2 * N) + 2 * n0 + 4 * j) = v;
    }
}

// ---------------------------------------------------------------------------
// Conv + gate from precomputed Bx and C_gate:
// y = tf32( Cg[s] * (w2*Bx[s] + w1*Bx[s-1] + w0*Bx[s-2]) )
// ---------------------------------------------------------------------------
__global__ void conv_gate_kernel(const float* __restrict__ conv_w,
                                 float* __restrict__ y) {
    const size_t total = (size_t)MTOT * (DD / 4);
    size_t idx = (size_t)blockIdx.x * blockDim.x + threadIdx.x;
    if (idx >= total) return;

    const int    d4 = (int)(idx % (DD / 4));
    const size_t bs = idx / (DD / 4);
    const int    s  = (int)(bs % SS);
    const int    d  = d4 * 4;

    float4 bx0 = *(const float4*)(g_Bx + bs * DD + d);
    float4 bx1 = (s >= 1) ? *(const float4*)(g_Bx + (bs - 1) * DD + d)
                          : make_float4(0.f, 0.f, 0.f, 0.f);
    float4 bx2 = (s >= 2) ? *(const float4*)(g_Bx + (bs - 2) * DD + d)
                          : make_float4(0.f, 0.f, 0.f, 0.f);
    float4 cg  = *(const float4*)(g_Cg + bs * DD + d);

    float o[4];
    const float* b0 = &bx0.x;
    const float* b1 = &bx1.x;
    const float* b2 = &bx2.x;
    const float* cgp = &cg.x;
    #pragma unroll
    for (int j = 0; j < 4; j++) {
        const int dj = d + j;
        const float w0 = conv_w[dj * LL + 0];
        const float w1 = conv_w[dj * LL + 1];
        const float w2 = conv_w[dj * LL + 2];
        float conv = w2 * b0[j] + w1 * b1[j] + w0 * b2[j];
        o[j] = f2tf32(cgp[j] * conv);
    }
    *(float4*)(y + bs * DD + d) = make_float4(o[0], o[1], o[2], o[3]);
}

// ---------------------------------------------------------------------------
extern "C" void kernel_launch(void* const* d_in, const int* in_sizes, int n_in,
                              void* d_out, int out_size) {
    const float* x      = (const float*)d_in[0];
    const float* W_in   = (const float*)d_in[1];
    const float* conv_w = (const float*)d_in[2];
    const float* W_out  = (const float*)d_in[3];
    float*       out    = (float*)d_out;

    float *Bx, *Cg, *y, *xc, *Win, *Wout;
    cudaGetSymbolAddress((void**)&Bx,   g_Bx);
    cudaGetSymbolAddress((void**)&Cg,   g_Cg);
    cudaGetSymbolAddress((void**)&y,    g_y);
    cudaGetSymbolAddress((void**)&xc,   g_xc);
    cudaGetSymbolAddress((void**)&Win,  g_Win);
    cudaGetSymbolAddress((void**)&Wout, g_Wout);

    cudaFuncSetAttribute(tf32_gemm, cudaFuncAttributeMaxDynamicSharedMemorySize, SMEM_BYTES);

    // Pre-passes: tf32 rounding (x) + weight transforms
    {
        size_t n4 = (size_t)MTOT * DD / 4;
        cvt_tf32_kernel<<<(unsigned)((n4 + 255) / 256), 256>>>(x, xc, n4);
        wtrans_kernel<1><<<dim3(TRIPLE / 256, DD / 8), 256>>>(W_in, Win, TRIPLE);
        wtrans_kernel<0><<<dim3(DD / 256, DD / 8), 256>>>(W_out, Wout, DD);
    }

    // GEMM1 (gated): writes Bx = B_gate*x_proj and C_gate directly
    tf32_gemm<<<dim3(TRIPLE / BN, MTOT / BM), 128, SMEM_BYTES>>>(
        xc, Win, nullptr, Bx, Cg, TRIPLE, DD, 1);

    // Conv + gate -> y (tf32-rounded)
    {
        size_t total = (size_t)MTOT * (DD / 4);
        conv_gate_kernel<<<(unsigned)((total + 255) / 256), 256>>>(conv_w, y);
    }

    // GEMM2: out = y @ W_out
    tf32_gemm<<<dim3(DD / BN, MTOT / BM), 128, SMEM_BYTES>>>(
        y, Wout, out, nullptr, nullptr, DD, DD, 0);
}